// round 15
// baseline (speedup 1.0000x reference)
#include <cuda_runtime.h>
#include <cuda_bf16.h>
#include <stdint.h>

#define C_DIM  50257
#define N_ROWS 8192
#define TOPK   5734          // int(0.7 * 8192)
#define BLK    256
#define N_B    1184          // 8 CTAs/SM x 148 SMs: one FULL wave (full occupancy)
#define N_A    (N_ROWS - N_B)   // 7008

// Scratch (no device allocation allowed).
__device__ float    g_loss[N_ROWS];
__device__ unsigned g_done = 0;   // B's row CTAs release-increment; CTA0 resets

__device__ __forceinline__ unsigned f2u_ord(float f) {
    unsigned b = __float_as_uint(f);
    return (b & 0x80000000u) ? ~b : (b | 0x80000000u);
}
__device__ __forceinline__ float u2f_ord(unsigned u) {
    unsigned b = (u & 0x80000000u) ? (u ^ 0x80000000u) : ~u;
    return __uint_as_float(b);
}

// ---------------------------------------------------------------------------
// Shared row-loss body (EXACT R6 hot loop, ~7 TB/s at 8 CTAs/SM).
// ---------------------------------------------------------------------------
__device__ __forceinline__ void row_loss_body(
    const float* __restrict__ inp,
    const void* __restrict__ tgt,
    int row)
{
    const float* __restrict__ x = inp + (size_t)row * C_DIM;
    const int tid = threadIdx.x;

    float s0 = 0.f, s1 = 0.f, s2 = 0.f, s3 = 0.f;

    // Scalar head to reach 16B alignment (row byte offset = 4*row mod 16).
    const int mis  = (int)(((uintptr_t)x & 15u) >> 2);
    const int head = (4 - mis) & 3;
    if (tid < head) s0 += __expf(__ldg(x + tid));

    const float4* __restrict__ xv = (const float4*)(x + head);
    const int nvec = (C_DIM - head) >> 2;                // float4 count

    int i = tid;
    #pragma unroll 1
    for (; i + 3 * BLK < nvec; i += 4 * BLK) {           // 4 LDG.128 in flight
        float4 a = __ldg(xv + i);
        float4 b = __ldg(xv + i + BLK);
        float4 c = __ldg(xv + i + 2 * BLK);
        float4 d = __ldg(xv + i + 3 * BLK);
        s0 += __expf(a.x); s1 += __expf(a.y); s2 += __expf(a.z); s3 += __expf(a.w);
        s0 += __expf(b.x); s1 += __expf(b.y); s2 += __expf(b.z); s3 += __expf(b.w);
        s0 += __expf(c.x); s1 += __expf(c.y); s2 += __expf(c.z); s3 += __expf(c.w);
        s0 += __expf(d.x); s1 += __expf(d.y); s2 += __expf(d.z); s3 += __expf(d.w);
    }
    for (; i < nvec; i += BLK) {
        float4 v = __ldg(xv + i);
        s0 += __expf(v.x); s1 += __expf(v.y); s2 += __expf(v.z); s3 += __expf(v.w);
    }
    // Scalar tail.
    for (int c = head + (nvec << 2) + tid; c < C_DIM; c += BLK)
        s0 += __expf(__ldg(x + c));

    float s = (s0 + s1) + (s2 + s3);

    #pragma unroll
    for (int o = 16; o > 0; o >>= 1)
        s += __shfl_down_sync(0xffffffffu, s, o);

    __shared__ float warp_sums[BLK / 32];
    if ((tid & 31) == 0) warp_sums[tid >> 5] = s;
    __syncthreads();

    if (tid < (BLK / 32)) {
        float v = warp_sums[tid];
        #pragma unroll
        for (int o = (BLK / 64); o > 0; o >>= 1)
            v += __shfl_down_sync(0xffu, v, o);
        if (tid == 0) {
            // dtype-robust target fetch: JAX w/o x64 downcasts int64->int32.
            const int* t32 = (const int*)tgt;
            bool is64 = (t32[1] == 0) & (t32[3] == 0) &
                        (t32[5] == 0) & (t32[7] == 0);
            long long t = is64 ? ((const long long*)tgt)[row]
                               : (long long)t32[row];
            if (t < 0 || t >= C_DIM) t = 0;   // defensive: never fault
            float xt = __ldg(x + (int)t);
            g_loss[row] = logf(v) - xt;
        }
    }
}

// ---------------------------------------------------------------------------
// Epilogue (cold, noinline): radix-select (MSB-first, 4x8-bit) of the k-th
// largest loss + tie-corrected deterministic mean. 256 threads, keys from L2.
// ---------------------------------------------------------------------------
__device__ __noinline__ void topk_epilogue(float* __restrict__ out)
{
    __shared__ unsigned hist[256];
    __shared__ unsigned sh_prefix, sh_krem;
    __shared__ float    wsum[BLK / 32];
    __shared__ unsigned wcnt[BLK / 32];

    const int tid  = threadIdx.x;
    const int lane = tid & 31;
    const int wid  = tid >> 5;

    if (tid == 0) { sh_prefix = 0u; sh_krem = TOPK; }

    for (int pass = 3; pass >= 0; pass--) {
        hist[tid] = 0u;                                // BLK == 256
        __syncthreads();

        const unsigned shift  = (unsigned)pass * 8u;
        const unsigned pmask  = (pass == 3) ? 0u : (0xFFFFFFFFu << (shift + 8));
        const unsigned prefix = sh_prefix;

        // Warp-aggregated histogram.
        #pragma unroll
        for (int j = 0; j < N_ROWS / BLK; j++) {
            unsigned u   = f2u_ord(__ldcg(&g_loss[tid + j * BLK]));
            bool     act = ((u & pmask) == prefix);
            unsigned am  = __ballot_sync(0xffffffffu, act);
            if (act) {
                unsigned bin   = (u >> shift) & 0xFFu;
                unsigned peers = __match_any_sync(am, bin);
                if (lane == __ffs(peers) - 1)
                    atomicAdd(&hist[bin], (unsigned)__popc(peers));
            }
        }
        __syncthreads();

        // Warp 0: suffix scan over 256 bins (8 bins/lane) + bucket find.
        if (wid == 0) {
            const unsigned krem = sh_krem;
            unsigned v[8];
            #pragma unroll
            for (int j = 0; j < 8; j++) v[j] = hist[lane * 8 + j];
            unsigned T = 0;
            #pragma unroll
            for (int j = 0; j < 8; j++) T += v[j];

            unsigned inc = T;                          // suffix across lanes
            #pragma unroll
            for (int off = 1; off < 32; off <<= 1) {
                unsigned o = __shfl_down_sync(0xffffffffu, inc, off);
                if (lane + off < 32) inc += o;
            }
            unsigned run = inc - T;                    // sum over lanes > lane
            #pragma unroll
            for (int j = 7; j >= 0; j--) {
                unsigned nxt = run;
                run += v[j];
                if (run >= krem && nxt < krem) {
                    sh_prefix = prefix | ((unsigned)(lane * 8 + j) << shift);
                    sh_krem   = krem - nxt;
                }
            }
        }
        __syncthreads();
    }

    const unsigned ut = sh_prefix;      // bit pattern of k-th largest loss

    // Sum of strictly-greater values + count (deterministic fixed tree).
    float    sg = 0.f;
    unsigned g  = 0;
    #pragma unroll
    for (int j = 0; j < N_ROWS / BLK; j++) {
        unsigned u = f2u_ord(__ldcg(&g_loss[tid + j * BLK]));
        if (u > ut) { sg += u2f_ord(u); g++; }
    }
    #pragma unroll
    for (int o = 16; o > 0; o >>= 1) {
        sg += __shfl_down_sync(0xffffffffu, sg, o);
        g  += __shfl_down_sync(0xffffffffu, g,  o);
    }
    if (lane == 0) { wsum[wid] = sg; wcnt[wid] = g; }
    __syncthreads();
    if (wid == 0 && lane < (BLK / 32)) {
        float    ss = wsum[lane];
        unsigned cc = wcnt[lane];
        #pragma unroll
        for (int o = (BLK / 64); o > 0; o >>= 1) {
            ss += __shfl_down_sync(0xffu, ss, o);
            cc += __shfl_down_sync(0xffu, cc, o);
        }
        if (lane == 0) {
            out[0]  = (ss + (float)(TOPK - cc) * u2f_ord(ut)) / (float)TOPK;
            g_done = 0;                 // reset for next graph replay
        }
    }
}

// ---------------------------------------------------------------------------
// Kernel A: rows [0, N_A). Pure streaming, no atomics, no fences.
// ---------------------------------------------------------------------------
__global__ __launch_bounds__(BLK) void row_loss_kernel(
    const float* __restrict__ inp,
    const void* __restrict__ tgt)
{
    row_loss_body(inp, tgt, blockIdx.x);
}

// ---------------------------------------------------------------------------
// Kernel B: grid N_B = 1184 (one FULL wave, 8 CTAs/SM — same occupancy as A).
// Each CTA streams one tail row (useful work replacing dead selector startup),
// publishes via release-RED; CTA 0 spin-waits then runs the epilogue.
// A's losses visible via stream order; B's via release/acquire.
// ---------------------------------------------------------------------------
__global__ __launch_bounds__(BLK) void tail_topk_kernel(
    const float* __restrict__ inp,
    const void* __restrict__ tgt,
    float* __restrict__ out)
{
    const int tid = threadIdx.x;

    // Phase 1: this CTA's row.
    row_loss_body(inp, tgt, N_A + (int)blockIdx.x);

    // Phase 2: publish (release orders the g_loss STG).
    if (tid == 0)
        asm volatile("red.release.gpu.global.add.u32 [%0], %1;"
                     :: "l"(&g_done), "r"(1u) : "memory");

    if (blockIdx.x != 0) return;       // only CTA 0 continues

    // Phase 3: wait for all N_B publications (CTA0 holds 1 of 1184 slots;
    // every other B CTA can always schedule -> no deadlock).
    if (tid == 0) {
        unsigned d;
        do {
            asm volatile("ld.acquire.gpu.global.u32 %0, [%1];"
                         : "=r"(d) : "l"(&g_done) : "memory");
            if (d < N_B) __nanosleep(256);
        } while (d < N_B);
    }
    __syncthreads();

    // Phase 4: selection epilogue.
    topk_epilogue(out);
}

// ---------------------------------------------------------------------------
extern "C" void kernel_launch(void* const* d_in, const int* in_sizes, int n_in,
                              void* d_out, int out_size)
{
    const float* inp = (const float*)d_in[0];   // [8192, 50257] f32
    const void*  tgt = d_in[1];                 // [8192] int32 or int64
    float*       out = (float*)d_out;           // scalar f32

    row_loss_kernel<<<N_A, BLK>>>(inp, tgt);
    tail_topk_kernel<<<N_B, BLK>>>(inp, tgt, out);
}

// round 17
// speedup vs baseline: 1.1693x; 1.1693x over previous
#include <cuda_runtime.h>
#include <cuda_bf16.h>
#include <stdint.h>

#define C_DIM  50257
#define N_ROWS 8192
#define TOPK   5734          // int(0.7 * 8192)
#define BLK    256
#define K2_GRID 148          // grid >= 148: low-grid issue throttle vanishes

// Scratch for per-row losses (no device allocation allowed).
__device__ float g_loss[N_ROWS];

// ---------------------------------------------------------------------------
// Kernel 1: one CTA per row. EXACT R6 body (~7 TB/s, best measured).
// ---------------------------------------------------------------------------
__global__ __launch_bounds__(BLK) void row_loss_kernel(
    const float* __restrict__ inp,
    const void* __restrict__ tgt)
{
    const int row = blockIdx.x;
    const float* __restrict__ x = inp + (size_t)row * C_DIM;
    const int tid = threadIdx.x;

    float s0 = 0.f, s1 = 0.f, s2 = 0.f, s3 = 0.f;

    // Scalar head to reach 16B alignment (row byte offset = 4*row mod 16).
    const int mis  = (int)(((uintptr_t)x & 15u) >> 2);
    const int head = (4 - mis) & 3;
    if (tid < head) s0 += __expf(__ldg(x + tid));

    const float4* __restrict__ xv = (const float4*)(x + head);
    const int nvec = (C_DIM - head) >> 2;                // float4 count

    int i = tid;
    #pragma unroll 1
    for (; i + 3 * BLK < nvec; i += 4 * BLK) {           // 4 LDG.128 in flight
        float4 a = __ldg(xv + i);
        float4 b = __ldg(xv + i + BLK);
        float4 c = __ldg(xv + i + 2 * BLK);
        float4 d = __ldg(xv + i + 3 * BLK);
        s0 += __expf(a.x); s1 += __expf(a.y); s2 += __expf(a.z); s3 += __expf(a.w);
        s0 += __expf(b.x); s1 += __expf(b.y); s2 += __expf(b.z); s3 += __expf(b.w);
        s0 += __expf(c.x); s1 += __expf(c.y); s2 += __expf(c.z); s3 += __expf(c.w);
        s0 += __expf(d.x); s1 += __expf(d.y); s2 += __expf(d.z); s3 += __expf(d.w);
    }
    for (; i < nvec; i += BLK) {
        float4 v = __ldg(xv + i);
        s0 += __expf(v.x); s1 += __expf(v.y); s2 += __expf(v.z); s3 += __expf(v.w);
    }
    // Scalar tail.
    for (int c = head + (nvec << 2) + tid; c < C_DIM; c += BLK)
        s0 += __expf(__ldg(x + c));

    float s = (s0 + s1) + (s2 + s3);

    #pragma unroll
    for (int o = 16; o > 0; o >>= 1)
        s += __shfl_down_sync(0xffffffffu, s, o);

    __shared__ float warp_sums[BLK / 32];
    if ((tid & 31) == 0) warp_sums[tid >> 5] = s;
    __syncthreads();

    if (tid < (BLK / 32)) {
        float v = warp_sums[tid];
        #pragma unroll
        for (int o = (BLK / 64); o > 0; o >>= 1)
            v += __shfl_down_sync(0xffu, v, o);
        if (tid == 0) {
            // dtype-robust target fetch: JAX w/o x64 downcasts int64->int32.
            const int* t32 = (const int*)tgt;
            bool is64 = (t32[1] == 0) & (t32[3] == 0) &
                        (t32[5] == 0) & (t32[7] == 0);
            long long t = is64 ? ((const long long*)tgt)[row]
                               : (long long)t32[row];
            if (t < 0 || t >= C_DIM) t = 0;   // defensive: never fault
            float xt = __ldg(x + (int)t);
            g_loss[row] = logf(v) - xt;
        }
    }
}

// ---------------------------------------------------------------------------
// Kernel 2: 148 CTAs x 1024 threads. Every CTA redundantly runs the EXACT R6
// register-resident radix-select (keys loaded ONCE into regs; 32 warps hide
// L2 latency); CTA 0 writes the scalar. grid=148 sidesteps the documented
// low-grid issue throttle; redundancy needs no cross-CTA sync (deterministic).
// ---------------------------------------------------------------------------
__device__ __forceinline__ unsigned f2u_ord(float f) {
    unsigned b = __float_as_uint(f);
    return (b & 0x80000000u) ? ~b : (b | 0x80000000u);
}
__device__ __forceinline__ float u2f_ord(unsigned u) {
    unsigned b = (u & 0x80000000u) ? (u ^ 0x80000000u) : ~u;
    return __uint_as_float(b);
}

__global__ __launch_bounds__(1024) void topk_mean_kernel(float* __restrict__ out)
{
    __shared__ unsigned hist[256];
    __shared__ unsigned sh_prefix, sh_krem;
    __shared__ float    wsum[32];
    __shared__ unsigned wcnt[32];

    const int tid  = threadIdx.x;       // 1024 threads
    const int lane = tid & 31;
    const int wid  = tid >> 5;

    // 8 keys per thread, register-resident across all passes.
    unsigned key[8];
    #pragma unroll
    for (int j = 0; j < 8; j++)
        key[j] = f2u_ord(g_loss[tid + j * 1024]);

    if (tid == 0) { sh_prefix = 0u; sh_krem = TOPK; }

    for (int pass = 3; pass >= 0; pass--) {
        if (tid < 256) hist[tid] = 0u;
        __syncthreads();                               // hist zero + prefix visible

        const unsigned shift  = (unsigned)pass * 8u;
        const unsigned pmask  = (pass == 3) ? 0u : (0xFFFFFFFFu << (shift + 8));
        const unsigned prefix = sh_prefix;

        #pragma unroll
        for (int j = 0; j < 8; j++) {
            unsigned u   = key[j];
            bool     act = ((u & pmask) == prefix);
            unsigned am  = __ballot_sync(0xffffffffu, act);
            if (act) {
                unsigned bin   = (u >> shift) & 0xFFu;
                unsigned peers = __match_any_sync(am, bin);
                if (lane == __ffs(peers) - 1)
                    atomicAdd(&hist[bin], (unsigned)__popc(peers));
            }
        }
        __syncthreads();                               // histogram complete

        // Warp 0: suffix scan over 256 bins (8 bins/lane) + bucket find.
        if (wid == 0) {
            const unsigned krem = sh_krem;
            unsigned v[8];
            #pragma unroll
            for (int j = 0; j < 8; j++) v[j] = hist[lane * 8 + j];

            unsigned T = 0;
            #pragma unroll
            for (int j = 0; j < 8; j++) T += v[j];

            unsigned inc = T;                          // suffix across lanes
            #pragma unroll
            for (int off = 1; off < 32; off <<= 1) {
                unsigned o = __shfl_down_sync(0xffffffffu, inc, off);
                if (lane + off < 32) inc += o;
            }
            unsigned run = inc - T;                    // sum over lanes > lane
            #pragma unroll
            for (int j = 7; j >= 0; j--) {
                unsigned nxt = run;                    // suffix of bin idx+1
                run += v[j];                           // suffix of this bin
                if (run >= krem && nxt < krem) {
                    sh_prefix = prefix | ((unsigned)(lane * 8 + j) << shift);
                    sh_krem   = krem - nxt;
                }
            }
        }
        __syncthreads();                               // new prefix visible
    }

    const unsigned ut = sh_prefix;      // bit pattern of k-th largest loss

    // Sum of strictly-greater values + count (deterministic fixed tree).
    float    sg = 0.f;
    unsigned g  = 0;
    #pragma unroll
    for (int j = 0; j < 8; j++) {
        unsigned u = key[j];
        if (u > ut) { sg += u2f_ord(u); g++; }
    }
    #pragma unroll
    for (int o = 16; o > 0; o >>= 1) {
        sg += __shfl_down_sync(0xffffffffu, sg, o);
        g  += __shfl_down_sync(0xffffffffu, g,  o);
    }
    if (lane == 0) { wsum[wid] = sg; wcnt[wid] = g; }
    __syncthreads();
    if (wid == 0) {
        float    s = wsum[lane];
        unsigned c = wcnt[lane];
        #pragma unroll
        for (int o = 16; o > 0; o >>= 1) {
            s += __shfl_down_sync(0xffffffffu, s, o);
            c += __shfl_down_sync(0xffffffffu, c, o);
        }
        if (lane == 0 && blockIdx.x == 0)
            out[0] = (s + (float)(TOPK - c) * u2f_ord(ut)) / (float)TOPK;
    }
}

// ---------------------------------------------------------------------------
extern "C" void kernel_launch(void* const* d_in, const int* in_sizes, int n_in,
                              void* d_out, int out_size)
{
    const float* inp = (const float*)d_in[0];   // [8192, 50257] f32
    const void*  tgt = d_in[1];                 // [8192] int32 or int64
    float*       out = (float*)d_out;           // scalar f32

    row_loss_kernel<<<N_ROWS, BLK>>>(inp, tgt);
    topk_mean_kernel<<<K2_GRID, 1024>>>(out);
}